// round 15
// baseline (speedup 1.0000x reference)
#include <cuda_runtime.h>
#include <cuda_fp16.h>
#include <math.h>
#include <cstdint>

#define SEQ   2048
#define DIM   4096
#define NH    32
#define NKV   8
#define HD    128
#define KVD   (NKV * HD)             /* 1024 */
#define QKV_W (DIM + 2 * KVD)        /* 6144: [q 4096 | k 1024 | v 1024] per row */
#define SCALE 0.08838834764831845f   /* 1/sqrt(128) */

// ---------------------------------------------------------------------------
// Scratch (__device__ globals — the sanctioned allocation mechanism)
// ---------------------------------------------------------------------------
__device__ __half g_qkvh[SEQ * QKV_W];     // fp16 qkv, RoPE + Q-scale pre-applied
__device__ __half g_xh[SEQ * DIM];
__device__ __half g_wAh[QKV_W * DIM];      // wq|wk|wv fused
__device__ __half g_woh[DIM * DIM];
__device__ __half g_ah[SEQ * DIM];         // flash output (fp16)

// ---------------------------------------------------------------------------
// helpers
// ---------------------------------------------------------------------------
__device__ __forceinline__ uint32_t smem_u32(const void* p) {
    uint32_t a;
    asm("{ .reg .u64 t; cvta.to.shared.u64 t, %1; cvt.u32.u64 %0, t; }"
        : "=r"(a) : "l"(p));
    return a;
}
__device__ __forceinline__ void cp_async16(uint32_t dst, const void* src) {
    asm volatile("cp.async.cg.shared.global [%0], [%1], 16;"
                 :: "r"(dst), "l"(src));
}
__device__ __forceinline__ void mma_fp16(float& d0, float& d1, float& d2, float& d3,
                                         uint32_t a0, uint32_t a1, uint32_t a2, uint32_t a3,
                                         uint32_t b0, uint32_t b1)
{
    asm volatile(
        "mma.sync.aligned.m16n8k16.row.col.f32.f16.f16.f32 "
        "{%0,%1,%2,%3}, {%4,%5,%6,%7}, {%8,%9}, {%0,%1,%2,%3};"
        : "+f"(d0), "+f"(d1), "+f"(d2), "+f"(d3)
        : "r"(a0), "r"(a1), "r"(a2), "r"(a3), "r"(b0), "r"(b1));
}
__device__ __forceinline__ void ldsm4(uint32_t& r0, uint32_t& r1, uint32_t& r2,
                                      uint32_t& r3, uint32_t a)
{
    asm volatile("ldmatrix.sync.aligned.m8n8.x4.shared.b16 {%0,%1,%2,%3}, [%4];"
                 : "=r"(r0), "=r"(r1), "=r"(r2), "=r"(r3) : "r"(a));
}
__device__ __forceinline__ void ldsm4t(uint32_t& r0, uint32_t& r1, uint32_t& r2,
                                       uint32_t& r3, uint32_t a)
{
    asm volatile("ldmatrix.sync.aligned.m8n8.x4.trans.shared.b16 {%0,%1,%2,%3}, [%4];"
                 : "=r"(r0), "=r"(r1), "=r"(r2), "=r"(r3) : "r"(a));
}
__device__ __forceinline__ uint32_t pack2h(float x, float y) {
    __half2 hv = __halves2half2(__float2half_rn(x), __float2half_rn(y));
    return *(uint32_t*)&hv;
}
__device__ __forceinline__ void conv4h(float4 v, uint2& h) {
    __half2 ha = __halves2half2(__float2half_rn(v.x), __float2half_rn(v.y));
    __half2 hb = __halves2half2(__float2half_rn(v.z), __float2half_rn(v.w));
    h = make_uint2(*(uint32_t*)&ha, *(uint32_t*)&hb);
}

// ---------------------------------------------------------------------------
// fp32 -> fp16 convert (vectorized x4)  — exact R12 version
// ---------------------------------------------------------------------------
__global__ void conv_kernel(const float* __restrict__ src,
                            __half* __restrict__ hi, int n4)
{
    int i = blockIdx.x * blockDim.x + threadIdx.x;
    if (i >= n4) return;
    float4 v = ((const float4*)src)[i];
    uint2 h;
    conv4h(v, h);
    ((uint2*)hi)[i] = h;
}

// ---------------------------------------------------------------------------
// HMMA GEMM (pure fp16): C = A[M,K]*B[N,K]^T, fp32 accum.
// 128x256 tile, warp 64x64 (2x4), BK=32, 4-stage cp.async, XOR swizzle.
// ROPE=true: rotary embedding on Q/K columns + 1/sqrt(d) folded into Q,
//            write fp16 (g_qkvh).  ROPE=false: write fp32.
// ---------------------------------------------------------------------------
#define AH3   0
#define BH3   (128 * 32)                 /* 4096  halfs */
#define STG3  (BH3 + 256 * 32)           /* 12288 halfs = 24576 B */
#define GEMM_SMEM (4 * STG3 * 2)         /* 98304 B */

template <bool ROPE>
__global__ void __launch_bounds__(256, 1) gemm_mma2(
    const __half* __restrict__ Ah,
    const __half* __restrict__ Bh,
    float* __restrict__ Cf, __half* __restrict__ Ch,
    const float* __restrict__ fc, const float* __restrict__ fs,
    int ldc, int K)
{
    extern __shared__ __half sm3[];
    const uint32_t sbase = smem_u32(sm3);
    const int tid = threadIdx.x;
    const int wid = tid >> 5, lane = tid & 31;
    const int warp_m = wid & 1, warp_n = wid >> 1;      // 2 x 4 warp grid
    const int g = lane >> 2, t = lane & 3;
    const int m0 = blockIdx.y * 128, n0 = blockIdx.x * 256;

    const int rl = lane & 15;
    const int sw = (rl >> 1) & 3;
    const int ch = lane >> 4;
    const uint32_t LM0 = rl * 32 + (((ch + 0) ^ sw) << 3);
    const uint32_t LM1 = rl * 32 + (((ch + 2) ^ sw) << 3);

    const __half* gAh = Ah + (size_t)m0 * K;
    const __half* gBh = Bh + (size_t)n0 * K;

    float d[4][8][4];
#pragma unroll
    for (int i = 0; i < 4; i++)
#pragma unroll
        for (int j = 0; j < 8; j++)
#pragma unroll
            for (int e = 0; e < 4; e++) d[i][j][e] = 0.f;

    const int nk = K / 32;

    auto issue = [&](int s, int buf) {
        const int koff = s * 32;
        const uint32_t stg = sbase + (uint32_t)buf * (STG3 * 2);
#pragma unroll
        for (int j = 0; j < 6; j++) {
            int idx = tid + j * 256;
            const __half* src;
            uint32_t off;
            int r;
            if (idx < 512) { r = idx >> 2;         src = gAh; off = AH3; }
            else           { r = (idx - 512) >> 2; src = gBh; off = BH3; }
            int c = idx & 3;
            int cs = c ^ ((r >> 1) & 3);
            cp_async16(stg + 2 * (off + r * 32 + cs * 8),
                       src + (size_t)r * K + koff + c * 8);
        }
        asm volatile("cp.async.commit_group;" ::: "memory");
    };

    issue(0, 0);
    if (nk > 1) issue(1, 1);
    if (nk > 2) issue(2, 2);

    for (int s = 0; s < nk; s++) {
        const int buf = s & 3;
        if (s + 2 < nk)      asm volatile("cp.async.wait_group 2;" ::: "memory");
        else if (s + 1 < nk) asm volatile("cp.async.wait_group 1;" ::: "memory");
        else                 asm volatile("cp.async.wait_group 0;" ::: "memory");
        __syncthreads();
        if (s + 3 < nk) issue(s + 3, (s + 3) & 3);

        const uint32_t stg = sbase + (uint32_t)buf * (STG3 * 2);

#pragma unroll
        for (int ks = 0; ks < 2; ks++) {
            const uint32_t LM = ks ? LM1 : LM0;
            uint32_t aH[4][4];
#pragma unroll
            for (int mt = 0; mt < 4; mt++) {
                uint32_t ab = stg + 2 * (AH3 + (warp_m * 64 + mt * 16) * 32 + LM);
                ldsm4(aH[mt][0], aH[mt][1], aH[mt][2], aH[mt][3], ab);
            }
#pragma unroll
            for (int ng = 0; ng < 4; ng++) {
                uint32_t bb = stg + 2 * (BH3 + (warp_n * 64 + ng * 16) * 32 + LM);
                uint32_t bh0, bh1, bh2, bh3;
                ldsm4(bh0, bh1, bh2, bh3, bb);
#pragma unroll
                for (int mt = 0; mt < 4; mt++) {
                    float* de = d[mt][2 * ng];
                    float* dc = d[mt][2 * ng + 1];
                    mma_fp16(de[0], de[1], de[2], de[3],
                             aH[mt][0], aH[mt][1], aH[mt][2], aH[mt][3], bh0, bh2);
                    mma_fp16(dc[0], dc[1], dc[2], dc[3],
                             aH[mt][0], aH[mt][1], aH[mt][2], aH[mt][3], bh1, bh3);
                }
            }
        }
        __syncthreads();
    }

    // epilogue
#pragma unroll
    for (int mt = 0; mt < 4; mt++) {
        const int row = m0 + warp_m * 64 + mt * 16 + g;
#pragma unroll
        for (int nt = 0; nt < 8; nt++) {
            const int col = n0 + warp_n * 64 + nt * 8 + 2 * t;
            if (ROPE) {
                float v0 = d[mt][nt][0], v1 = d[mt][nt][1];
                float v2 = d[mt][nt][2], v3 = d[mt][nt][3];
                if (col < DIM + KVD) {   // Q or K column pair: rotate
                    const int p = (col >> 1) & 63;
                    float c0 = fc[row * 64 + p],       s0 = fs[row * 64 + p];
                    float c1 = fc[(row + 8) * 64 + p], s1 = fs[(row + 8) * 64 + p];
                    float r0 = v0 * c0 - v1 * s0, i0n = v0 * s0 + v1 * c0;
                    float r1 = v2 * c1 - v3 * s1, i1n = v2 * s1 + v3 * c1;
                    v0 = r0; v1 = i0n; v2 = r1; v3 = i1n;
                    if (col < DIM) {     // Q: fold in 1/sqrt(d)
                        v0 *= SCALE; v1 *= SCALE; v2 *= SCALE; v3 *= SCALE;
                    }
                }
                *(uint32_t*)(Ch + (size_t)row * ldc + col)       = pack2h(v0, v1);
                *(uint32_t*)(Ch + (size_t)(row + 8) * ldc + col) = pack2h(v2, v3);
            } else {
                *(float2*)(Cf + (size_t)row * ldc + col) =
                    make_float2(d[mt][nt][0], d[mt][nt][1]);
                *(float2*)(Cf + (size_t)(row + 8) * ldc + col) =
                    make_float2(d[mt][nt][2], d[mt][nt][3]);
            }
        }
    }
}

// ---------------------------------------------------------------------------
// Tensor-core flash attention (fp16 operands, fp32 accum).
// Block = 128 q x 1 head, 8 warps x 16 rows.  Longest-first scheduling.
// 3-stage KV ring, ONE __syncthreads per tile.  Scale pre-folded into Q.
// smem (halfs): Q[128][136] | kv0{K V} | kv1{K V} | kv2{K V}
// ---------------------------------------------------------------------------
#define FS     136
#define KVBUF  17408                      /* halfs per K+V buffer            */
#define FLASH_SMEM2 ((17408 + 3 * KVBUF) * 2)   /* 139264 B */

__global__ void __launch_bounds__(256, 1) flash_mma()
{
    extern __shared__ __half sb[];
    const uint32_t sb2 = smem_u32(sb);
    const int qt = (int)gridDim.x - 1 - (int)blockIdx.x;  // longest tiles first
    const int h = blockIdx.y;
    const int q0 = qt * 128;
    const int kvh = h >> 2;
    const int tid = threadIdx.x;
    const int wid = tid >> 5, lane = tid & 31;
    const int g = lane >> 2, t = lane & 3;
    const int rmin = q0 + wid * 16;
    const uint32_t LM = (lane & 15) * FS + ((lane >> 4) << 3);

    const __half* qkvh = g_qkvh;
    const int nkt = 2 * (qt + 1);

    // Q tile: 128 rows x 16 chunks of 16 B, cp.async (joins group 0 with KV0)
    const __half* qb = qkvh + (size_t)q0 * QKV_W + h * HD;
#pragma unroll
    for (int p = 0; p < 8; p++) {
        int i = tid + p * 256;
        int r = i >> 4, c8 = i & 15;
        cp_async16(sb2 + 2 * (r * FS + c8 * 8), qb + (size_t)r * QKV_W + c8 * 8);
    }

    // K/V stage loader: 64 rows x 16 chunks each
    auto kv_issue = [&](int kt, int buf) {
        const __half* kb = qkvh + (size_t)(kt * 64) * QKV_W + DIM + kvh * HD;
        const __half* vb = kb + KVD;
        const uint32_t kdst = sb2 + 2 * (17408 + buf * KVBUF);
        const uint32_t vdst = kdst + 2 * 8704;
#pragma unroll
        for (int p = 0; p < 4; p++) {
            int i = tid + p * 256;
            int r = i >> 4, c8 = i & 15;
            uint32_t o2 = 2 * (r * FS + c8 * 8);
            cp_async16(kdst + o2, kb + (size_t)r * QKV_W + c8 * 8);
            cp_async16(vdst + o2, vb + (size_t)r * QKV_W + c8 * 8);
        }
        asm volatile("cp.async.commit_group;" ::: "memory");
    };

    kv_issue(0, 0);                  // group 0 = Q + KV(0)
    if (nkt > 1) kv_issue(1, 1);     // group 1 = KV(1)

    float m0 = -1e30f, m1 = -1e30f, l0 = 0.f, l1 = 0.f;
    float o[16][4];
#pragma unroll
    for (int i = 0; i < 16; i++)
#pragma unroll
        for (int e = 0; e < 4; e++) o[i][e] = 0.f;

    int buf = 0;                     // kt % 3, tracked incrementally

    for (int kt = 0; kt < nkt; kt++) {
        // wait for group kt to land (<=1 newer group may stay in flight)
        if (kt + 1 < nkt) asm volatile("cp.async.wait_group 1;" ::: "memory");
        else              asm volatile("cp.async.wait_group 0;" ::: "memory");
        __syncthreads();   // single barrier: all warps done with tile kt-1,
                           // buffer (kt+2)%3 == (kt-1)%3 is free to refill
        if (kt + 2 < nkt) {
            int nb = buf + 2; if (nb >= 3) nb -= 3;
            kv_issue(kt + 2, nb);
        }

        if (kt * 64 <= rmin + 15) {            // warp not fully masked
            const uint32_t KHO = 17408 + buf * KVBUF;
            const uint32_t VHO = KHO + 8704;

            float s[8][4];
#pragma unroll
            for (int i = 0; i < 8; i++)
#pragma unroll
                for (int e = 0; e < 4; e++) s[i][e] = 0.f;

#pragma unroll
            for (int ks = 0; ks < 8; ks++) {
                uint32_t qa = sb2 + 2 * (wid * 16 * FS + LM + ks * 16);
                uint32_t qh0, qh1, qh2, qh3;
                ldsm4(qh0, qh1, qh2, qh3, qa);
#pragma unroll
                for (int np = 0; np < 4; np++) {
                    uint32_t ka = sb2 + 2 * (KHO + np * 16 * FS + LM + ks * 16);
                    uint32_t kh0, kh1, kh2, kh3;
                    ldsm4(kh0, kh1, kh2, kh3, ka);
                    float* se = s[2 * np];
                    float* so = s[2 * np + 1];
                    mma_fp16(se[0], se[1], se[2], se[3], qh0, qh1, qh2, qh3, kh0, kh2);
                    mma_fp16(so[0], so[1], so[2], so[3], qh0, qh1, qh2, qh3, kh1, kh3);
                }
            }

            // causal mask (scale already folded into Q)
            const bool dm = (kt * 64 + 63) > rmin;
            if (dm) {
#pragma unroll
                for (int nt = 0; nt < 8; nt++) {
                    int colb = kt * 64 + nt * 8 + 2 * t;
#pragma unroll
                    for (int e = 0; e < 4; e++)
                        if ((colb + (e & 1)) > (rmin + g + (e >> 1) * 8))
                            s[nt][e] = -1e30f;
                }
            }

            float rm0 = -1e30f, rm1 = -1e30f;
#pragma unroll
            for (int nt = 0; nt < 8; nt++) {
                rm0 = fmaxf(rm0, fmaxf(s[nt][0], s[nt][1]));
                rm1 = fmaxf(rm1, fmaxf(s[nt][2], s[nt][3]));
            }
            rm0 = fmaxf(rm0, __shfl_xor_sync(0xffffffffu, rm0, 1));
            rm0 = fmaxf(rm0, __shfl_xor_sync(0xffffffffu, rm0, 2));
            rm1 = fmaxf(rm1, __shfl_xor_sync(0xffffffffu, rm1, 1));
            rm1 = fmaxf(rm1, __shfl_xor_sync(0xffffffffu, rm1, 2));
            float mn0 = fmaxf(m0, rm0), mn1 = fmaxf(m1, rm1);
            float a0 = __expf(m0 - mn0), a1 = __expf(m1 - mn1);
            m0 = mn0; m1 = mn1;
            float ls0 = 0.f, ls1 = 0.f;
#pragma unroll
            for (int nt = 0; nt < 8; nt++) {
                s[nt][0] = __expf(s[nt][0] - mn0);
                s[nt][1] = __expf(s[nt][1] - mn0);
                s[nt][2] = __expf(s[nt][2] - mn1);
                s[nt][3] = __expf(s[nt][3] - mn1);
                ls0 += s[nt][0] + s[nt][1];
                ls1 += s[nt][2] + s[nt][3];
            }
            ls0 += __shfl_xor_sync(0xffffffffu, ls0, 1);
            ls0 += __shfl_xor_sync(0xffffffffu, ls0, 2);
            ls1 += __shfl_xor_sync(0xffffffffu, ls1, 1);
            ls1 += __shfl_xor_sync(0xffffffffu, ls1, 2);
            l0 = l0 * a0 + ls0;
            l1 = l1 * a1 + ls1;
#pragma unroll
            for (int nt = 0; nt < 16; nt++) {
                o[nt][0] *= a0; o[nt][1] *= a0;
                o[nt][2] *= a1; o[nt][3] *= a1;
            }

            uint32_t pah[4][4];
#pragma unroll
            for (int k2 = 0; k2 < 4; k2++) {
                pah[k2][0] = pack2h(s[2 * k2][0],     s[2 * k2][1]);
                pah[k2][1] = pack2h(s[2 * k2][2],     s[2 * k2][3]);
                pah[k2][2] = pack2h(s[2 * k2 + 1][0], s[2 * k2 + 1][1]);
                pah[k2][3] = pack2h(s[2 * k2 + 1][2], s[2 * k2 + 1][3]);
            }

#pragma unroll
            for (int k2 = 0; k2 < 4; k2++) {
#pragma unroll
                for (int np = 0; np < 8; np++) {
                    uint32_t va = sb2 + 2 * (VHO + k2 * 16 * FS + LM + np * 16);
                    uint32_t vh0, vh1, vh2, vh3;
                    ldsm4t(vh0, vh1, vh2, vh3, va);
                    float* oe = o[2 * np];
                    float* oo = o[2 * np + 1];
                    mma_fp16(oe[0], oe[1], oe[2], oe[3],
                             pah[k2][0], pah[k2][1], pah[k2][2], pah[k2][3], vh0, vh1);
                    mma_fp16(oo[0], oo[1], oo[2], oo[3],
                             pah[k2][0], pah[k2][1], pah[k2][2], pah[k2][3], vh2, vh3);
                }
            }
        }

        if (++buf == 3) buf = 0;
    }

    // epilogue: normalize, write fp16 (A-side of WO GEMM)
    float i0 = 1.f / l0, i1 = 1.f / l1;
    __half* oh0 = g_ah + (size_t)(rmin + g) * DIM + h * HD;
    __half* oh1 = g_ah + (size_t)(rmin + g + 8) * DIM + h * HD;
#pragma unroll
    for (int nt = 0; nt < 16; nt++) {
        int col = nt * 8 + 2 * t;
        *(uint32_t*)(oh0 + col) = pack2h(o[nt][0] * i0, o[nt][1] * i0);
        *(uint32_t*)(oh1 + col) = pack2h(o[nt][2] * i1, o[nt][3] * i1);
    }
}

// ---------------------------------------------------------------------------
extern "C" void kernel_launch(void* const* d_in, const int* in_sizes, int n_in,
                              void* d_out, int out_size)
{
    const float* x  = (const float*)d_in[0];
    const float* wq = (const float*)d_in[1];
    const float* wk = (const float*)d_in[2];
    const float* wv = (const float*)d_in[3];
    const float* wo = (const float*)d_in[4];
    const float* fc = (const float*)d_in[7];
    const float* fs = (const float*)d_in[8];
    float* out = (float*)d_out;
    (void)in_sizes; (void)n_in; (void)out_size;

    static __half* qkvh = nullptr;
    static __half *xh, *wAh, *woh, *ah;
    if (!qkvh) {   // first call is the uncaptured correctness run
        cudaGetSymbolAddress((void**)&qkvh, g_qkvh);
        cudaGetSymbolAddress((void**)&xh, g_xh);
        cudaGetSymbolAddress((void**)&wAh, g_wAh);
        cudaGetSymbolAddress((void**)&woh, g_woh);
        cudaGetSymbolAddress((void**)&ah, g_ah);
        cudaFuncSetAttribute(gemm_mma2<true>,
                             cudaFuncAttributeMaxDynamicSharedMemorySize, GEMM_SMEM);
        cudaFuncSetAttribute(gemm_mma2<false>,
                             cudaFuncAttributeMaxDynamicSharedMemorySize, GEMM_SMEM);
        cudaFuncSetAttribute(flash_mma,
                             cudaFuncAttributeMaxDynamicSharedMemorySize, FLASH_SMEM2);
    }

    // fp32 -> fp16 conversions (exact R12 scheme)
    conv_kernel<<<(SEQ * DIM / 4 + 255) / 256, 256>>>(x, xh, SEQ * DIM / 4);
    conv_kernel<<<(DIM * DIM / 4 + 255) / 256, 256>>>(wq, wAh, DIM * DIM / 4);
    conv_kernel<<<(KVD * DIM / 4 + 255) / 256, 256>>>(
        wk, wAh + (size_t)DIM * DIM, KVD * DIM / 4);
    conv_kernel<<<(KVD * DIM / 4 + 255) / 256, 256>>>(
        wv, wAh + (size_t)(DIM + KVD) * DIM, KVD * DIM / 4);
    conv_kernel<<<(DIM * DIM / 4 + 255) / 256, 256>>>(wo, woh, DIM * DIM / 4);

    // Fused QKV projection + RoPE + Q-scale -> g_qkvh [S, 6144] fp16
    gemm_mma2<true><<<dim3(QKV_W / 256, SEQ / 128), 256, GEMM_SMEM>>>(
        xh, wAh, nullptr, qkvh, fc, fs, QKV_W, DIM);

    // Causal GQA flash attention (3-stage ring, 1 barrier/tile) -> g_ah
    flash_mma<<<dim3(SEQ / 128, NH), 256, FLASH_SMEM2>>>();

    // Output projection -> fp32 out
    gemm_mma2<false><<<dim3(DIM / 256, SEQ / 128), 256, GEMM_SMEM>>>(
        ah, woh, out, nullptr, nullptr, nullptr, DIM, DIM);
}

// round 16
// speedup vs baseline: 1.5256x; 1.5256x over previous
#include <cuda_runtime.h>
#include <cuda_fp16.h>
#include <math.h>
#include <cstdint>

#define SEQ   2048
#define DIM   4096
#define NH    32
#define NKV   8
#define HD    128
#define KVD   (NKV * HD)             /* 1024 */
#define QKV_W (DIM + 2 * KVD)        /* 6144: [q 4096 | k 1024 | v 1024] per row */
#define SCALE 0.08838834764831845f   /* 1/sqrt(128) */

// ---------------------------------------------------------------------------
// Scratch (__device__ globals — the sanctioned allocation mechanism)
// ---------------------------------------------------------------------------
__device__ __half g_qkvh[SEQ * QKV_W];     // fp16 qkv, RoPE + Q-scale pre-applied
__device__ __half g_xh[SEQ * DIM];
__device__ __half g_wAh[QKV_W * DIM];      // wq|wk|wv fused
__device__ __half g_woh[DIM * DIM];
__device__ __half g_ah[SEQ * DIM];         // flash output (fp16)

// ---------------------------------------------------------------------------
// helpers
// ---------------------------------------------------------------------------
__device__ __forceinline__ uint32_t smem_u32(const void* p) {
    uint32_t a;
    asm("{ .reg .u64 t; cvta.to.shared.u64 t, %1; cvt.u32.u64 %0, t; }"
        : "=r"(a) : "l"(p));
    return a;
}
__device__ __forceinline__ void cp_async16(uint32_t dst, const void* src) {
    asm volatile("cp.async.cg.shared.global [%0], [%1], 16;"
                 :: "r"(dst), "l"(src));
}
__device__ __forceinline__ void mma_fp16(float& d0, float& d1, float& d2, float& d3,
                                         uint32_t a0, uint32_t a1, uint32_t a2, uint32_t a3,
                                         uint32_t b0, uint32_t b1)
{
    asm volatile(
        "mma.sync.aligned.m16n8k16.row.col.f32.f16.f16.f32 "
        "{%0,%1,%2,%3}, {%4,%5,%6,%7}, {%8,%9}, {%0,%1,%2,%3};"
        : "+f"(d0), "+f"(d1), "+f"(d2), "+f"(d3)
        : "r"(a0), "r"(a1), "r"(a2), "r"(a3), "r"(b0), "r"(b1));
}
__device__ __forceinline__ void ldsm4(uint32_t& r0, uint32_t& r1, uint32_t& r2,
                                      uint32_t& r3, uint32_t a)
{
    asm volatile("ldmatrix.sync.aligned.m8n8.x4.shared.b16 {%0,%1,%2,%3}, [%4];"
                 : "=r"(r0), "=r"(r1), "=r"(r2), "=r"(r3) : "r"(a));
}
__device__ __forceinline__ void ldsm4t(uint32_t& r0, uint32_t& r1, uint32_t& r2,
                                       uint32_t& r3, uint32_t a)
{
    asm volatile("ldmatrix.sync.aligned.m8n8.x4.trans.shared.b16 {%0,%1,%2,%3}, [%4];"
                 : "=r"(r0), "=r"(r1), "=r"(r2), "=r"(r3) : "r"(a));
}
__device__ __forceinline__ uint32_t pack2h(float x, float y) {
    __half2 hv = __halves2half2(__float2half_rn(x), __float2half_rn(y));
    return *(uint32_t*)&hv;
}
__device__ __forceinline__ void conv4h(float4 v, uint2& h) {
    __half2 ha = __halves2half2(__float2half_rn(v.x), __float2half_rn(v.y));
    __half2 hb = __halves2half2(__float2half_rn(v.z), __float2half_rn(v.w));
    h = make_uint2(*(uint32_t*)&ha, *(uint32_t*)&hb);
}

// ---------------------------------------------------------------------------
// fp32 -> fp16 convert (vectorized x4)  — exact R12 version
// ---------------------------------------------------------------------------
__global__ void conv_kernel(const float* __restrict__ src,
                            __half* __restrict__ hi, int n4)
{
    int i = blockIdx.x * blockDim.x + threadIdx.x;
    if (i >= n4) return;
    float4 v = ((const float4*)src)[i];
    uint2 h;
    conv4h(v, h);
    ((uint2*)hi)[i] = h;
}

// ---------------------------------------------------------------------------
// HMMA GEMM (pure fp16): C = A[M,K]*B[N,K]^T, fp32 accum.
// 128x256 tile, warp 64x64 (2x4), BK=32, 4-stage cp.async, XOR swizzle.
// ROPE=true: rotary embedding on Q/K columns + 1/sqrt(d) folded into Q,
//            write fp16 (g_qkvh).  ROPE=false: write fp32.
// ---------------------------------------------------------------------------
#define AH3   0
#define BH3   (128 * 32)                 /* 4096  halfs */
#define STG3  (BH3 + 256 * 32)           /* 12288 halfs = 24576 B */
#define GEMM_SMEM (4 * STG3 * 2)         /* 98304 B */

template <bool ROPE>
__global__ void __launch_bounds__(256, 1) gemm_mma2(
    const __half* __restrict__ Ah,
    const __half* __restrict__ Bh,
    float* __restrict__ Cf, __half* __restrict__ Ch,
    const float* __restrict__ fc, const float* __restrict__ fs,
    int ldc, int K)
{
    extern __shared__ __half sm3[];
    const uint32_t sbase = smem_u32(sm3);
    const int tid = threadIdx.x;
    const int wid = tid >> 5, lane = tid & 31;
    const int warp_m = wid & 1, warp_n = wid >> 1;      // 2 x 4 warp grid
    const int g = lane >> 2, t = lane & 3;
    const int m0 = blockIdx.y * 128, n0 = blockIdx.x * 256;

    const int rl = lane & 15;
    const int sw = (rl >> 1) & 3;
    const int ch = lane >> 4;
    const uint32_t LM0 = rl * 32 + (((ch + 0) ^ sw) << 3);
    const uint32_t LM1 = rl * 32 + (((ch + 2) ^ sw) << 3);

    const __half* gAh = Ah + (size_t)m0 * K;
    const __half* gBh = Bh + (size_t)n0 * K;

    float d[4][8][4];
#pragma unroll
    for (int i = 0; i < 4; i++)
#pragma unroll
        for (int j = 0; j < 8; j++)
#pragma unroll
            for (int e = 0; e < 4; e++) d[i][j][e] = 0.f;

    const int nk = K / 32;

    auto issue = [&](int s, int buf) {
        const int koff = s * 32;
        const uint32_t stg = sbase + (uint32_t)buf * (STG3 * 2);
#pragma unroll
        for (int j = 0; j < 6; j++) {
            int idx = tid + j * 256;
            const __half* src;
            uint32_t off;
            int r;
            if (idx < 512) { r = idx >> 2;         src = gAh; off = AH3; }
            else           { r = (idx - 512) >> 2; src = gBh; off = BH3; }
            int c = idx & 3;
            int cs = c ^ ((r >> 1) & 3);
            cp_async16(stg + 2 * (off + r * 32 + cs * 8),
                       src + (size_t)r * K + koff + c * 8);
        }
        asm volatile("cp.async.commit_group;" ::: "memory");
    };

    issue(0, 0);
    if (nk > 1) issue(1, 1);
    if (nk > 2) issue(2, 2);

    for (int s = 0; s < nk; s++) {
        const int buf = s & 3;
        if (s + 2 < nk)      asm volatile("cp.async.wait_group 2;" ::: "memory");
        else if (s + 1 < nk) asm volatile("cp.async.wait_group 1;" ::: "memory");
        else                 asm volatile("cp.async.wait_group 0;" ::: "memory");
        __syncthreads();
        if (s + 3 < nk) issue(s + 3, (s + 3) & 3);

        const uint32_t stg = sbase + (uint32_t)buf * (STG3 * 2);

#pragma unroll
        for (int ks = 0; ks < 2; ks++) {
            const uint32_t LM = ks ? LM1 : LM0;
            uint32_t aH[4][4];
#pragma unroll
            for (int mt = 0; mt < 4; mt++) {
                uint32_t ab = stg + 2 * (AH3 + (warp_m * 64 + mt * 16) * 32 + LM);
                ldsm4(aH[mt][0], aH[mt][1], aH[mt][2], aH[mt][3], ab);
            }
#pragma unroll
            for (int ng = 0; ng < 4; ng++) {
                uint32_t bb = stg + 2 * (BH3 + (warp_n * 64 + ng * 16) * 32 + LM);
                uint32_t bh0, bh1, bh2, bh3;
                ldsm4(bh0, bh1, bh2, bh3, bb);
#pragma unroll
                for (int mt = 0; mt < 4; mt++) {
                    float* de = d[mt][2 * ng];
                    float* dc = d[mt][2 * ng + 1];
                    mma_fp16(de[0], de[1], de[2], de[3],
                             aH[mt][0], aH[mt][1], aH[mt][2], aH[mt][3], bh0, bh2);
                    mma_fp16(dc[0], dc[1], dc[2], dc[3],
                             aH[mt][0], aH[mt][1], aH[mt][2], aH[mt][3], bh1, bh3);
                }
            }
        }
        __syncthreads();
    }

    // epilogue
#pragma unroll
    for (int mt = 0; mt < 4; mt++) {
        const int row = m0 + warp_m * 64 + mt * 16 + g;
#pragma unroll
        for (int nt = 0; nt < 8; nt++) {
            const int col = n0 + warp_n * 64 + nt * 8 + 2 * t;
            if (ROPE) {
                float v0 = d[mt][nt][0], v1 = d[mt][nt][1];
                float v2 = d[mt][nt][2], v3 = d[mt][nt][3];
                if (col < DIM + KVD) {   // Q or K column pair: rotate
                    const int p = (col >> 1) & 63;
                    float c0 = fc[row * 64 + p],       s0 = fs[row * 64 + p];
                    float c1 = fc[(row + 8) * 64 + p], s1 = fs[(row + 8) * 64 + p];
                    float r0 = v0 * c0 - v1 * s0, i0n = v0 * s0 + v1 * c0;
                    float r1 = v2 * c1 - v3 * s1, i1n = v2 * s1 + v3 * c1;
                    v0 = r0; v1 = i0n; v2 = r1; v3 = i1n;
                    if (col < DIM) {     // Q: fold in 1/sqrt(d)
                        v0 *= SCALE; v1 *= SCALE; v2 *= SCALE; v3 *= SCALE;
                    }
                }
                *(uint32_t*)(Ch + (size_t)row * ldc + col)       = pack2h(v0, v1);
                *(uint32_t*)(Ch + (size_t)(row + 8) * ldc + col) = pack2h(v2, v3);
            } else {
                *(float2*)(Cf + (size_t)row * ldc + col) =
                    make_float2(d[mt][nt][0], d[mt][nt][1]);
                *(float2*)(Cf + (size_t)(row + 8) * ldc + col) =
                    make_float2(d[mt][nt][2], d[mt][nt][3]);
            }
        }
    }
}

// ---------------------------------------------------------------------------
// Tensor-core flash attention (fp16 operands, fp32 accum).
// Block = 128 q x 1 head, 8 warps x 16 rows.  Longest-first scheduling.
// Exact R12 pipeline: 2-stage KV double-buffer, 2 barriers/tile.
// Scale pre-folded into Q.
// smem (halfs): Q[128][136] | buf0{K[64][136] V[64][136]} | buf1{K V}
// ---------------------------------------------------------------------------
#define FS     136
#define KVBUF  17408                      /* halfs per K+V buffer            */
#define FLASH_SMEM2 ((17408 + 2 * KVBUF) * 2)   /* 104448 B */

__global__ void __launch_bounds__(256, 1) flash_mma()
{
    extern __shared__ __half sb[];
    const uint32_t sb2 = smem_u32(sb);
    const int qt = (int)gridDim.x - 1 - (int)blockIdx.x;  // longest tiles first
    const int h = blockIdx.y;
    const int q0 = qt * 128;
    const int kvh = h >> 2;
    const int tid = threadIdx.x;
    const int wid = tid >> 5, lane = tid & 31;
    const int g = lane >> 2, t = lane & 3;
    const int rmin = q0 + wid * 16;
    const uint32_t LM = (lane & 15) * FS + ((lane >> 4) << 3);

    const __half* qkvh = g_qkvh;
    const int nkt = 2 * (qt + 1);

    // Q tile: 128 rows x 16 chunks of 16 B, cp.async (group 0 with KV0)
    const __half* qb = qkvh + (size_t)q0 * QKV_W + h * HD;
#pragma unroll
    for (int p = 0; p < 8; p++) {
        int i = tid + p * 256;
        int r = i >> 4, c8 = i & 15;
        cp_async16(sb2 + 2 * (r * FS + c8 * 8), qb + (size_t)r * QKV_W + c8 * 8);
    }

    // K/V stage loader: 64 rows x 16 chunks each
    auto kv_issue = [&](int kt, int buf) {
        const __half* kb = qkvh + (size_t)(kt * 64) * QKV_W + DIM + kvh * HD;
        const __half* vb = kb + KVD;
        const uint32_t kdst = sb2 + 2 * (17408 + buf * KVBUF);
        const uint32_t vdst = kdst + 2 * 8704;
#pragma unroll
        for (int p = 0; p < 4; p++) {
            int i = tid + p * 256;
            int r = i >> 4, c8 = i & 15;
            uint32_t o2 = 2 * (r * FS + c8 * 8);
            cp_async16(kdst + o2, kb + (size_t)r * QKV_W + c8 * 8);
            cp_async16(vdst + o2, vb + (size_t)r * QKV_W + c8 * 8);
        }
        asm volatile("cp.async.commit_group;" ::: "memory");
    };

    kv_issue(0, 0);   // group 0 = Q + KV(0)

    float m0 = -1e30f, m1 = -1e30f, l0 = 0.f, l1 = 0.f;
    float o[16][4];
#pragma unroll
    for (int i = 0; i < 16; i++)
#pragma unroll
        for (int e = 0; e < 4; e++) o[i][e] = 0.f;

    for (int kt = 0; kt < nkt; kt++) {
        const int buf = kt & 1;
        __syncthreads();                          // prior compute on buf^1 done
        if (kt + 1 < nkt) {
            kv_issue(kt + 1, buf ^ 1);
            asm volatile("cp.async.wait_group 1;" ::: "memory");
        } else {
            asm volatile("cp.async.wait_group 0;" ::: "memory");
        }
        __syncthreads();

        if (kt * 64 > rmin + 15) continue;        // warp fully masked: skip

        const uint32_t KHO = 17408 + buf * KVBUF;
        const uint32_t VHO = KHO + 8704;

        float s[8][4];
#pragma unroll
        for (int i = 0; i < 8; i++)
#pragma unroll
            for (int e = 0; e < 4; e++) s[i][e] = 0.f;

#pragma unroll
        for (int ks = 0; ks < 8; ks++) {
            uint32_t qa = sb2 + 2 * (wid * 16 * FS + LM + ks * 16);
            uint32_t qh0, qh1, qh2, qh3;
            ldsm4(qh0, qh1, qh2, qh3, qa);
#pragma unroll
            for (int np = 0; np < 4; np++) {
                uint32_t ka = sb2 + 2 * (KHO + np * 16 * FS + LM + ks * 16);
                uint32_t kh0, kh1, kh2, kh3;
                ldsm4(kh0, kh1, kh2, kh3, ka);
                float* se = s[2 * np];
                float* so = s[2 * np + 1];
                mma_fp16(se[0], se[1], se[2], se[3], qh0, qh1, qh2, qh3, kh0, kh2);
                mma_fp16(so[0], so[1], so[2], so[3], qh0, qh1, qh2, qh3, kh1, kh3);
            }
        }

        // causal mask (scale already folded into Q)
        const bool dm = (kt * 64 + 63) > rmin;
        if (dm) {
#pragma unroll
            for (int nt = 0; nt < 8; nt++) {
                int colb = kt * 64 + nt * 8 + 2 * t;
#pragma unroll
                for (int e = 0; e < 4; e++)
                    if ((colb + (e & 1)) > (rmin + g + (e >> 1) * 8))
                        s[nt][e] = -1e30f;
            }
        }

        float rm0 = -1e30f, rm1 = -1e30f;
#pragma unroll
        for (int nt = 0; nt < 8; nt++) {
            rm0 = fmaxf(rm0, fmaxf(s[nt][0], s[nt][1]));
            rm1 = fmaxf(rm1, fmaxf(s[nt][2], s[nt][3]));
        }
        rm0 = fmaxf(rm0, __shfl_xor_sync(0xffffffffu, rm0, 1));
        rm0 = fmaxf(rm0, __shfl_xor_sync(0xffffffffu, rm0, 2));
        rm1 = fmaxf(rm1, __shfl_xor_sync(0xffffffffu, rm1, 1));
        rm1 = fmaxf(rm1, __shfl_xor_sync(0xffffffffu, rm1, 2));
        float mn0 = fmaxf(m0, rm0), mn1 = fmaxf(m1, rm1);
        float a0 = __expf(m0 - mn0), a1 = __expf(m1 - mn1);
        m0 = mn0; m1 = mn1;
        float ls0 = 0.f, ls1 = 0.f;
#pragma unroll
        for (int nt = 0; nt < 8; nt++) {
            s[nt][0] = __expf(s[nt][0] - mn0);
            s[nt][1] = __expf(s[nt][1] - mn0);
            s[nt][2] = __expf(s[nt][2] - mn1);
            s[nt][3] = __expf(s[nt][3] - mn1);
            ls0 += s[nt][0] + s[nt][1];
            ls1 += s[nt][2] + s[nt][3];
        }
        ls0 += __shfl_xor_sync(0xffffffffu, ls0, 1);
        ls0 += __shfl_xor_sync(0xffffffffu, ls0, 2);
        ls1 += __shfl_xor_sync(0xffffffffu, ls1, 1);
        ls1 += __shfl_xor_sync(0xffffffffu, ls1, 2);
        l0 = l0 * a0 + ls0;
        l1 = l1 * a1 + ls1;
#pragma unroll
        for (int nt = 0; nt < 16; nt++) {
            o[nt][0] *= a0; o[nt][1] *= a0;
            o[nt][2] *= a1; o[nt][3] *= a1;
        }

        uint32_t pah[4][4];
#pragma unroll
        for (int k2 = 0; k2 < 4; k2++) {
            pah[k2][0] = pack2h(s[2 * k2][0],     s[2 * k2][1]);
            pah[k2][1] = pack2h(s[2 * k2][2],     s[2 * k2][3]);
            pah[k2][2] = pack2h(s[2 * k2 + 1][0], s[2 * k2 + 1][1]);
            pah[k2][3] = pack2h(s[2 * k2 + 1][2], s[2 * k2 + 1][3]);
        }

#pragma unroll
        for (int k2 = 0; k2 < 4; k2++) {
#pragma unroll
            for (int np = 0; np < 8; np++) {
                uint32_t va = sb2 + 2 * (VHO + k2 * 16 * FS + LM + np * 16);
                uint32_t vh0, vh1, vh2, vh3;
                ldsm4t(vh0, vh1, vh2, vh3, va);
                float* oe = o[2 * np];
                float* oo = o[2 * np + 1];
                mma_fp16(oe[0], oe[1], oe[2], oe[3],
                         pah[k2][0], pah[k2][1], pah[k2][2], pah[k2][3], vh0, vh1);
                mma_fp16(oo[0], oo[1], oo[2], oo[3],
                         pah[k2][0], pah[k2][1], pah[k2][2], pah[k2][3], vh2, vh3);
            }
        }
    }

    // epilogue: normalize, write fp16 (A-side of WO GEMM)
    float i0 = 1.f / l0, i1 = 1.f / l1;
    __half* oh0 = g_ah + (size_t)(rmin + g) * DIM + h * HD;
    __half* oh1 = g_ah + (size_t)(rmin + g + 8) * DIM + h * HD;
#pragma unroll
    for (int nt = 0; nt < 16; nt++) {
        int col = nt * 8 + 2 * t;
        *(uint32_t*)(oh0 + col) = pack2h(o[nt][0] * i0, o[nt][1] * i0);
        *(uint32_t*)(oh1 + col) = pack2h(o[nt][2] * i1, o[nt][3] * i1);
    }
}

// ---------------------------------------------------------------------------
extern "C" void kernel_launch(void* const* d_in, const int* in_sizes, int n_in,
                              void* d_out, int out_size)
{
    const float* x  = (const float*)d_in[0];
    const float* wq = (const float*)d_in[1];
    const float* wk = (const float*)d_in[2];
    const float* wv = (const float*)d_in[3];
    const float* wo = (const float*)d_in[4];
    const float* fc = (const float*)d_in[7];
    const float* fs = (const float*)d_in[8];
    float* out = (float*)d_out;
    (void)in_sizes; (void)n_in; (void)out_size;

    static __half* qkvh = nullptr;
    static __half *xh, *wAh, *woh, *ah;
    if (!qkvh) {   // first call is the uncaptured correctness run
        cudaGetSymbolAddress((void**)&qkvh, g_qkvh);
        cudaGetSymbolAddress((void**)&xh, g_xh);
        cudaGetSymbolAddress((void**)&wAh, g_wAh);
        cudaGetSymbolAddress((void**)&woh, g_woh);
        cudaGetSymbolAddress((void**)&ah, g_ah);
        cudaFuncSetAttribute(gemm_mma2<true>,
                             cudaFuncAttributeMaxDynamicSharedMemorySize, GEMM_SMEM);
        cudaFuncSetAttribute(gemm_mma2<false>,
                             cudaFuncAttributeMaxDynamicSharedMemorySize, GEMM_SMEM);
        cudaFuncSetAttribute(flash_mma,
                             cudaFuncAttributeMaxDynamicSharedMemorySize, FLASH_SMEM2);
    }

    // fp32 -> fp16 conversions (exact R12 scheme)
    conv_kernel<<<(SEQ * DIM / 4 + 255) / 256, 256>>>(x, xh, SEQ * DIM / 4);
    conv_kernel<<<(DIM * DIM / 4 + 255) / 256, 256>>>(wq, wAh, DIM * DIM / 4);
    conv_kernel<<<(KVD * DIM / 4 + 255) / 256, 256>>>(
        wk, wAh + (size_t)DIM * DIM, KVD * DIM / 4);
    conv_kernel<<<(KVD * DIM / 4 + 255) / 256, 256>>>(
        wv, wAh + (size_t)(DIM + KVD) * DIM, KVD * DIM / 4);
    conv_kernel<<<(DIM * DIM / 4 + 255) / 256, 256>>>(wo, woh, DIM * DIM / 4);

    // Fused QKV projection + RoPE + Q-scale -> g_qkvh [S, 6144] fp16
    gemm_mma2<true><<<dim3(QKV_W / 256, SEQ / 128), 256, GEMM_SMEM>>>(
        xh, wAh, nullptr, qkvh, fc, fs, QKV_W, DIM);

    // Causal GQA flash attention (R12 pipeline) -> g_ah
    flash_mma<<<dim3(SEQ / 128, NH), 256, FLASH_SMEM2>>>();

    // Output projection -> fp32 out
    gemm_mma2<false><<<dim3(DIM / 256, SEQ / 128), 256, GEMM_SMEM>>>(
        ah, woh, out, nullptr, nullptr, nullptr, DIM, DIM);
}